// round 11
// baseline (speedup 1.0000x reference)
#include <cuda_runtime.h>

#define BB 64
#define SS 512
#define KK 7
#define SEGB 9              // segments per batch
#define NBLK (BB * SEGB)    // 576 blocks, one wave
#define NSEG 18             // half-segment matrices per batch

typedef unsigned long long ull;

// scratch (allocation-free rule: __device__ globals)
__device__ float g_M[NBLK * 2 * 49];     // half-segment matrices (log2)
__device__ float g_nump[NBLK];           // numerator partials (per block)
__device__ int   g_cntp[NBLK];           // mask-count partials (per block)
__device__ float g_em0[BB * KK];         // raw emissions row 0 per batch
__device__ unsigned int g_bcnt[BB];      // per-batch completion (wraps at 9)
__device__ unsigned int g_done = 0;      // batch completion (wraps at 64)
__device__ float g_llh = 0.f;            // llh accumulator (self-resetting)

// ---------------------------------------------------------------------------
__device__ __forceinline__ float ex2f(float x) {
    float y; asm("ex2.approx.f32 %0, %1;" : "=f"(y) : "f"(x)); return y;
}
__device__ __forceinline__ float lg2f(float x) {
    float y; asm("lg2.approx.f32 %0, %1;" : "=f"(y) : "f"(x)); return y;
}
__device__ __forceinline__ ull pk2(float lo, float hi) {
    ull r; asm("mov.b64 %0, {%1,%2};" : "=l"(r) : "f"(lo), "f"(hi)); return r;
}
__device__ __forceinline__ void upk2(ull p, float& lo, float& hi) {
    asm("mov.b64 {%0,%1}, %2;" : "=f"(lo), "=f"(hi) : "l"(p));
}
__device__ __forceinline__ ull fma2(ull a, ull b, ull c) {
    ull d; asm("fma.rn.f32x2 %0, %1, %2, %3;" : "=l"(d) : "l"(a), "l"(b), "l"(c));
    return d;
}

// ---------------------------------------------------------------------------
// ONE kernel, 576 blocks (one wave). Block (b, s): stream rows
// [b*512 + s*57, +n) with the proven streamer; emissions stay in smem; two
// half-segment transfer matrices in parallel (shuffle recursion); one atomic
// per block; elected per-batch combine; elected global scalar write.
// ---------------------------------------------------------------------------
__global__ __launch_bounds__(128, 4) void k_one(const float4* __restrict__ x4,
                                                const float* __restrict__ W,
                                                const float* __restrict__ bias,
                                                const void* __restrict__ gt,
                                                const unsigned char* __restrict__ mask,
                                                const float* __restrict__ start_t,
                                                const float* __restrict__ end_t,
                                                const float* __restrict__ trans,
                                                float* __restrict__ out) {
    const int t = threadIdx.x;
    const int lane = t & 31, warp = t >> 5;
    const int g = blockIdx.x;
    const int b = g / SEGB, s = g - b * SEGB;
    const int n = (s == 8) ? 56 : 57;
    const long row0 = (long)b * SS + s * 57;
    const float L2E = 1.4426950408889634f, LN2 = 0.6931471805599453f;

    __shared__ float wsum[4][57][8];
    __shared__ float em_s[57][8];
    __shared__ float trans_s[49];
    __shared__ int msk_s[57];
    __shared__ int s_mw, s_gw, s_last;

    // ---- warp-parallel dtype-width detection (warp 1; overlaps W load) ----
    if (warp == 1) {
        unsigned char v0 = mask[lane], v1 = mask[lane + 32];
        unsigned bm = __ballot_sync(0xffffffffu,
                                    ((lane & 3) && v0) || (((lane + 32) & 3) && v1));
        unsigned b4 = __ballot_sync(0xffffffffu,
                                    (((lane & 7) == 4) && v0) ||
                                    ((((lane + 32) & 7) == 4) && v1));
        int w1 = ((const int*)gt)[2 * lane + 1];
        int w2 = ((const int*)gt)[2 * (lane + 32) + 1];
        unsigned bg = __ballot_sync(0xffffffffu, (w1 | w2) != 0);
        if (lane == 0) {
            s_mw = bm ? 1 : (b4 ? 4 : 8);
            s_gw = bg ? 1 : 2;
        }
    }
    if (t < 49) trans_s[t] = trans[t];

    // ================= phase 1: streaming GEMV (R7-identical) =================
    ull w01[8], w23[8], w45[8];
    float w6[8];
#pragma unroll
    for (int jj = 0; jj < 2; jj++) {
        const float4* wp4 = (const float4*)(W + (t * 4 + jj * 512) * 7);
        float wb[28];
#pragma unroll
        for (int q4 = 0; q4 < 7; q4++) {
            float4 v = wp4[q4];
            wb[q4 * 4 + 0] = v.x; wb[q4 * 4 + 1] = v.y;
            wb[q4 * 4 + 2] = v.z; wb[q4 * 4 + 3] = v.w;
        }
#pragma unroll
        for (int q = 0; q < 4; q++) {
            int si = jj * 4 + q;
            w01[si] = pk2(wb[q * 7 + 0], wb[q * 7 + 1]);
            w23[si] = pk2(wb[q * 7 + 2], wb[q * 7 + 3]);
            w45[si] = pk2(wb[q * 7 + 4], wb[q * 7 + 5]);
            w6[si] = wb[q * 7 + 6];
        }
    }

#define DO_ROW(RR, X0, X1)                                                      \
    {                                                                           \
        float xq[8] = {X0.x, X0.y, X0.z, X0.w, X1.x, X1.y, X1.z, X1.w};         \
        ull c01 = 0, c23 = 0, c45 = 0;                                          \
        float c6 = 0.f;                                                         \
        _Pragma("unroll") for (int si = 0; si < 8; si++) {                      \
            ull xx = pk2(xq[si], xq[si]);                                       \
            c01 = fma2(xx, w01[si], c01);                                       \
            c23 = fma2(xx, w23[si], c23);                                       \
            c45 = fma2(xx, w45[si], c45);                                       \
            c6 = fmaf(xq[si], w6[si], c6);                                      \
        }                                                                       \
        float a[7];                                                             \
        upk2(c01, a[0], a[1]); upk2(c23, a[2], a[3]); upk2(c45, a[4], a[5]);    \
        a[6] = c6;                                                              \
        float tt[7];                                                            \
        _Pragma("unroll") for (int k = 0; k < 7; k++)                           \
            tt[k] = __shfl_xor_sync(0xffffffffu, a[k], 16);                     \
        bool hh = (lane & 16);                                                  \
        float v0 = hh ? a[4] + tt[4] : a[0] + tt[0];                            \
        float v1 = hh ? a[5] + tt[5] : a[1] + tt[1];                            \
        float v2 = hh ? a[6] + tt[6] : a[2] + tt[2];                            \
        float v3 = hh ? 0.f : a[3] + tt[3];                                     \
        float s0 = __shfl_xor_sync(0xffffffffu, v0, 8);                         \
        float s1 = __shfl_xor_sync(0xffffffffu, v1, 8);                         \
        float s2 = __shfl_xor_sync(0xffffffffu, v2, 8);                         \
        float s3 = __shfl_xor_sync(0xffffffffu, v3, 8);                         \
        bool b3p = (lane & 8);                                                  \
        float u0 = b3p ? v2 + s2 : v0 + s0;                                     \
        float u1 = b3p ? v3 + s3 : v1 + s1;                                     \
        float p0 = __shfl_xor_sync(0xffffffffu, u0, 4);                         \
        float p1 = __shfl_xor_sync(0xffffffffu, u1, 4);                         \
        float wv = (lane & 4) ? u1 + p1 : u0 + p0;                              \
        wv += __shfl_xor_sync(0xffffffffu, wv, 2);                              \
        wv += __shfl_xor_sync(0xffffffffu, wv, 1);                              \
        int k7 = (lane >> 2) & 7;                                               \
        if (((lane & 3) == 0) && (k7 < 7)) wsum[warp][RR][k7] = wv;             \
    }

    float4 buf[4][2];
#pragma unroll
    for (int u = 0; u < 4; u++) {
        buf[u][0] = __ldcs(&x4[(row0 + u) * 256 + t]);
        buf[u][1] = __ldcs(&x4[(row0 + u) * 256 + 128 + t]);
    }

#pragma unroll 1
    for (int rb = 0; rb < n; rb += 4) {
#pragma unroll
        for (int u = 0; u < 4; u++) {
            const int r = rb + u;
            if (r < n) {
                float4 X0 = buf[u][0], X1 = buf[u][1];
                const int pr = r + 4;
                if (pr < n) {
                    buf[u][0] = __ldcs(&x4[(row0 + pr) * 256 + t]);
                    buf[u][1] = __ldcs(&x4[(row0 + pr) * 256 + 128 + t]);
                }
                if (warp == 0) {
                    const int fr = r + 12;
                    if (fr < n) {
                        const char* p = (const char*)(x4 + (row0 + fr) * 256) + lane * 128;
                        asm volatile("prefetch.global.L2 [%0];" :: "l"(p));
                    }
                }
                DO_ROW(r, X0, X1);
            }
        }
    }
#undef DO_ROW
    __syncthreads();

    // ---- combine warp partials -> em_s (raw); stage masks; em0 ----
    const int mw = s_mw, gw = s_gw;
    for (int idx = t; idx < n * 8; idx += 128) {
        int r = idx >> 3, k = idx & 7;
        float e = 0.f;
        if (k < 7)
            e = wsum[0][r][k] + wsum[1][r][k] + wsum[2][r][k] + wsum[3][r][k] + bias[k];
        em_s[r][k] = e;
    }
    if (t < n) msk_s[t] = mask[(row0 + t) * mw] ? 1 : 0;
    __syncthreads();

    if (s == 0 && t < 7) g_em0[b * 7 + t] = em_s[0][t];

    // ---- recursion: two 64-thread groups, one half-segment each ----
    {
        const int grp = t >> 6;            // 0 or 1
        const int u = t & 63;
        const int i = u >> 3, j = u & 7;
        const bool act = (i < 7) && (j < 7);
        const int jj = (j < 7) ? j : 0;
        const int len0 = (n + 1) >> 1;
        const int base = grp ? len0 : 0;
        const int len = grp ? (n - len0) : len0;

        float Tr[7];
#pragma unroll
        for (int k = 0; k < 7; k++)
            Tr[k] = act ? ex2f(trans_s[k * 7 + jj] * L2E) : 0.f;

        float v = (act && i == j) ? 1.f : 0.f;
        int mexp = 0;

#pragma unroll 1
        for (int st = 0; st < len; st++) {
            const int lt = base + st;
            float e = ex2f(em_s[lt][jj] * L2E);
            int mk = msk_s[lt];
            if (s == 0 && lt == 0) mk = 0;   // global step 0 excluded
            float nv = 0.f;
#pragma unroll
            for (int k = 0; k < 7; k++)
                nv = fmaf(__shfl_sync(0xffffffffu, v, k, 8), Tr[k], nv);
            if (mk) v = nv * e;
            if (((st & 3) == 3) || (st == len - 1)) {
                float rs = v;
                rs += __shfl_xor_sync(0xffffffffu, rs, 4, 8);
                rs += __shfl_xor_sync(0xffffffffu, rs, 2, 8);
                rs += __shfl_xor_sync(0xffffffffu, rs, 1, 8);
                int eb = ((__float_as_int(rs) >> 23) & 255) - 127;
                eb = (rs > 0.f) ? eb : 0;
                v *= __int_as_float((127 - eb) << 23);   // * 2^-eb
                mexp += eb;
            }
        }
        if (act)
            g_M[(long)(g * 2 + grp) * 49 + i * 7 + j] = (float)mexp + lg2f(v);
    }

    // ---- numerator partial for this block's n timesteps (warp 0) ----
    if (warp == 0) {
        float ns = 0.f;
        int ncn = 0;
#pragma unroll
        for (int q = 0; q < 2; q++) {
            int lt = lane + q * 32;
            if (lt < n) {
                long t_abs = row0 + lt;
                int gc = ((const int*)gt)[t_abs * gw];
                int m = msk_s[lt];
                ncn += m;
                float emv = em_s[lt][gc];
                if (t_abs == 0) {
                    ns += start_t[gc] + emv;
                } else {
                    int gp = ((const int*)gt)[(t_abs - 1) * gw];
                    ns += m ? (trans_s[gp * 7 + gc] + emv) : 0.f;
                }
            }
        }
#pragma unroll
        for (int off = 16; off; off >>= 1) {
            ns += __shfl_xor_sync(0xffffffffu, ns, off);
            ncn += __shfl_xor_sync(0xffffffffu, ncn, off);
        }
        if (lane == 0) { g_nump[g] = ns; g_cntp[g] = ncn; }
    }

    // ---- publish + per-batch election ----
    __threadfence();
    __syncthreads();
    if (t == 0) {
        unsigned int old = atomicInc(&g_bcnt[b], SEGB - 1);
        s_last = (old == SEGB - 1) ? 1 : 0;
    }
    __syncthreads();
    if (!s_last || warp != 0) return;
    __threadfence();

    // ---- batch combine (warp 0 of the finisher; inputs L2-hot) ----
    {
        const int j = lane & 7;
        const int jj = (j < 7) ? j : 0;

        float p = (lane < SEGB) ? __ldcg(&g_nump[b * SEGB + lane]) : 0.f;
        int cn = (lane < SEGB) ? __ldcg(&g_cntp[b * SEGB + lane]) : 0;
#pragma unroll
        for (int off = 16; off; off >>= 1) {
            p += __shfl_xor_sync(0xffffffffu, p, off);
            cn += __shfl_xor_sync(0xffffffffu, cn, off);
        }
        const float num = p + end_t[((const int*)gt)[((long)b * SS + cn - 1) * gw]];

        float a = (j < 7) ? (start_t[jj] + __ldcg(&g_em0[b * 7 + jj])) * L2E : -1e30f;
        float M[7], M2[7];
        const long mb = (long)b * NSEG * 49;
#pragma unroll
        for (int i2 = 0; i2 < 7; i2++)
            M[i2] = __ldcg(&g_M[mb + i2 * 7 + jj]);

        for (int ch = 0; ch < NSEG; ch++) {
            if (ch + 1 < NSEG) {
#pragma unroll
                for (int i2 = 0; i2 < 7; i2++)
                    M2[i2] = __ldcg(&g_M[mb + (long)(ch + 1) * 49 + i2 * 7 + jj]);
            }
            float mx = -1e30f;
            float vv[7];
#pragma unroll
            for (int i2 = 0; i2 < 7; i2++) {
                vv[i2] = __shfl_sync(0xffffffffu, a, i2, 8) + M[i2];
                mx = fmaxf(mx, vv[i2]);
            }
            float sum = 0.f;
#pragma unroll
            for (int i2 = 0; i2 < 7; i2++) sum += ex2f(vv[i2] - mx);
            float anew = mx + lg2f(sum);
            a = (j < 7) ? anew : -1e30f;
#pragma unroll
            for (int i2 = 0; i2 < 7; i2++) M[i2] = M2[i2];
        }

        float z = (j < 7) ? a + end_t[jj] * L2E : -1e30f;
        float mz = z;
#pragma unroll
        for (int off = 4; off; off >>= 1)
            mz = fmaxf(mz, __shfl_xor_sync(0xffffffffu, mz, off, 8));
        float se = ex2f(z - mz);
#pragma unroll
        for (int off = 4; off; off >>= 1)
            se += __shfl_xor_sync(0xffffffffu, se, off, 8);
        const float denom = (mz + lg2f(se)) * LN2;

        if (lane == 0) {
            atomicAdd(&g_llh, num - denom);
            __threadfence();
            unsigned int old = atomicInc(&g_done, BB - 1);
            if (old == BB - 1) {
                float tot = atomicExch(&g_llh, 0.f);
                out[0] = -tot / (float)BB;
            }
        }
    }
}

// ---------------------------------------------------------------------------
extern "C" void kernel_launch(void* const* d_in, const int* in_sizes, int n_in,
                              void* d_out, int out_size) {
    const float4* x = (const float4*)d_in[0];
    const void* gt = d_in[1];
    const unsigned char* mask = (const unsigned char*)d_in[2];
    const float* W = (const float*)d_in[3];
    const float* bias = (const float*)d_in[4];
    const float* start_t = (const float*)d_in[5];
    const float* end_t = (const float*)d_in[6];
    const float* trans = (const float*)d_in[7];
    float* out = (float*)d_out;

    k_one<<<NBLK, 128>>>(x, W, bias, gt, mask, start_t, end_t, trans, out);
}

// round 12
// speedup vs baseline: 1.0548x; 1.0548x over previous
#include <cuda_runtime.h>

#define BB 64
#define SS 512
#define KK 7
#define NCHUNK 16
#define NBLK 512            // 8 blocks per batch, 64 rows each

typedef unsigned long long ull;

// scratch (allocation-free rule: __device__ globals)
__device__ float g_M[BB * NCHUNK * 49];  // chunk transfer matrices (log2)
__device__ float g_nump[NBLK];           // numerator partials (per block)
__device__ int   g_cntp[NBLK];           // mask-count partials (per block)
__device__ float g_em0[BB * KK];         // log2-domain emissions row 0 per batch
__device__ unsigned int g_bcnt[BB];      // per-batch completion (wraps at 8)
__device__ unsigned int g_done = 0;      // batch completion (wraps at 64)
__device__ float g_llh = 0.f;            // llh accumulator (self-resetting)

// ---------------------------------------------------------------------------
__device__ __forceinline__ float ex2f(float x) {
    float y; asm("ex2.approx.f32 %0, %1;" : "=f"(y) : "f"(x)); return y;
}
__device__ __forceinline__ float lg2f(float x) {
    float y; asm("lg2.approx.f32 %0, %1;" : "=f"(y) : "f"(x)); return y;
}
__device__ __forceinline__ ull pk2(float lo, float hi) {
    ull r; asm("mov.b64 %0, {%1,%2};" : "=l"(r) : "f"(lo), "f"(hi)); return r;
}
__device__ __forceinline__ void upk2(ull p, float& lo, float& hi) {
    asm("mov.b64 {%0,%1}, %2;" : "=f"(lo), "=f"(hi) : "l"(p));
}
__device__ __forceinline__ ull fma2(ull a, ull b, ull c) {
    ull d; asm("fma.rn.f32x2 %0, %1, %2, %3;" : "=l"(d) : "l"(a), "l"(b), "l"(c));
    return d;
}

// ---------------------------------------------------------------------------
// ONE kernel (R10 geometry). Stream 64 rows; emissions PRE-EXPONENTIATED once
// into smem (MUFU dedup); exp(trans) precomputed once into smem; two chunks
// recursed in parallel; one atomic per block; elected combines.
// ---------------------------------------------------------------------------
__global__ __launch_bounds__(128, 4) void k_one(const float4* __restrict__ x4,
                                                const float* __restrict__ W,
                                                const float* __restrict__ bias,
                                                const void* __restrict__ gt,
                                                const unsigned char* __restrict__ mask,
                                                const float* __restrict__ start_t,
                                                const float* __restrict__ end_t,
                                                const float* __restrict__ trans,
                                                float* __restrict__ out) {
    const int t = threadIdx.x;
    const int lane = t & 31, warp = t >> 5;
    const int g = blockIdx.x;
    const int b = g >> 3, cc = g & 7;
    const long row0 = (long)g * 64;
    const float L2E = 1.4426950408889634f, LN2 = 0.6931471805599453f;

    __shared__ float wsum[4][64][8];    // 8 KB
    __shared__ float em_s[64][8];       // PRE-EXP emissions: 2^(em*L2E)
    __shared__ float trans_s[49];       // raw trans
    __shared__ float trans_e[49];       // 2^(trans*L2E)
    __shared__ int msk_s[64];
    __shared__ int s_mw, s_gw, s_last;

    // ---- warp-parallel dtype-width detection (warp 1; overlaps W load) ----
    if (warp == 1) {
        unsigned char v0 = mask[lane], v1 = mask[lane + 32];
        unsigned bm = __ballot_sync(0xffffffffu,
                                    ((lane & 3) && v0) || (((lane + 32) & 3) && v1));
        unsigned b4 = __ballot_sync(0xffffffffu,
                                    (((lane & 7) == 4) && v0) ||
                                    ((((lane + 32) & 7) == 4) && v1));
        int w1 = ((const int*)gt)[2 * lane + 1];
        int w2 = ((const int*)gt)[2 * (lane + 32) + 1];
        unsigned bg = __ballot_sync(0xffffffffu, (w1 | w2) != 0);
        if (lane == 0) {
            s_mw = bm ? 1 : (b4 ? 4 : 8);
            s_gw = bg ? 1 : 2;
        }
    }
    if (t < 49) trans_s[t] = trans[t];

    // ================= phase 1: streaming GEMV (R7-identical) =================
    ull w01[8], w23[8], w45[8];
    float w6[8];
#pragma unroll
    for (int jj = 0; jj < 2; jj++) {
        const float4* wp4 = (const float4*)(W + (t * 4 + jj * 512) * 7);
        float wb[28];
#pragma unroll
        for (int q4 = 0; q4 < 7; q4++) {
            float4 v = wp4[q4];
            wb[q4 * 4 + 0] = v.x; wb[q4 * 4 + 1] = v.y;
            wb[q4 * 4 + 2] = v.z; wb[q4 * 4 + 3] = v.w;
        }
#pragma unroll
        for (int q = 0; q < 4; q++) {
            int s = jj * 4 + q;
            w01[s] = pk2(wb[q * 7 + 0], wb[q * 7 + 1]);
            w23[s] = pk2(wb[q * 7 + 2], wb[q * 7 + 3]);
            w45[s] = pk2(wb[q * 7 + 4], wb[q * 7 + 5]);
            w6[s] = wb[q * 7 + 6];
        }
    }

#define DO_ROW(RR, X0, X1)                                                      \
    {                                                                           \
        float xq[8] = {X0.x, X0.y, X0.z, X0.w, X1.x, X1.y, X1.z, X1.w};         \
        ull c01 = 0, c23 = 0, c45 = 0;                                          \
        float c6 = 0.f;                                                         \
        _Pragma("unroll") for (int s = 0; s < 8; s++) {                         \
            ull xx = pk2(xq[s], xq[s]);                                         \
            c01 = fma2(xx, w01[s], c01);                                        \
            c23 = fma2(xx, w23[s], c23);                                        \
            c45 = fma2(xx, w45[s], c45);                                        \
            c6 = fmaf(xq[s], w6[s], c6);                                        \
        }                                                                       \
        float a[7];                                                             \
        upk2(c01, a[0], a[1]); upk2(c23, a[2], a[3]); upk2(c45, a[4], a[5]);    \
        a[6] = c6;                                                              \
        float tt[7];                                                            \
        _Pragma("unroll") for (int k = 0; k < 7; k++)                           \
            tt[k] = __shfl_xor_sync(0xffffffffu, a[k], 16);                     \
        bool hh = (lane & 16);                                                  \
        float v0 = hh ? a[4] + tt[4] : a[0] + tt[0];                            \
        float v1 = hh ? a[5] + tt[5] : a[1] + tt[1];                            \
        float v2 = hh ? a[6] + tt[6] : a[2] + tt[2];                            \
        float v3 = hh ? 0.f : a[3] + tt[3];                                     \
        float s0 = __shfl_xor_sync(0xffffffffu, v0, 8);                         \
        float s1 = __shfl_xor_sync(0xffffffffu, v1, 8);                         \
        float s2 = __shfl_xor_sync(0xffffffffu, v2, 8);                         \
        float s3 = __shfl_xor_sync(0xffffffffu, v3, 8);                         \
        bool b3p = (lane & 8);                                                  \
        float u0 = b3p ? v2 + s2 : v0 + s0;                                     \
        float u1 = b3p ? v3 + s3 : v1 + s1;                                     \
        float p0 = __shfl_xor_sync(0xffffffffu, u0, 4);                         \
        float p1 = __shfl_xor_sync(0xffffffffu, u1, 4);                         \
        float wv = (lane & 4) ? u1 + p1 : u0 + p0;                              \
        wv += __shfl_xor_sync(0xffffffffu, wv, 2);                              \
        wv += __shfl_xor_sync(0xffffffffu, wv, 1);                              \
        int k7 = (lane >> 2) & 7;                                               \
        if (((lane & 3) == 0) && (k7 < 7)) wsum[warp][RR][k7] = wv;             \
    }

    float4 buf[4][2];
#pragma unroll
    for (int u = 0; u < 4; u++) {
        buf[u][0] = __ldcs(&x4[(row0 + u) * 256 + t]);
        buf[u][1] = __ldcs(&x4[(row0 + u) * 256 + 128 + t]);
    }

#pragma unroll 1
    for (int rb = 0; rb < 64; rb += 4) {
#pragma unroll
        for (int u = 0; u < 4; u++) {
            const int r = rb + u;
            float4 X0 = buf[u][0], X1 = buf[u][1];
            const int pr = r + 4;
            if (pr < 64) {
                buf[u][0] = __ldcs(&x4[(row0 + pr) * 256 + t]);
                buf[u][1] = __ldcs(&x4[(row0 + pr) * 256 + 128 + t]);
            }
            if (warp == 0) {
                const int fr = r + 12;
                if (fr < 64) {
                    const char* p = (const char*)(x4 + (row0 + fr) * 256) + lane * 128;
                    asm volatile("prefetch.global.L2 [%0];" :: "l"(p));
                }
            }
            DO_ROW(r, X0, X1);
        }
    }
#undef DO_ROW
    __syncthreads();

    // ---- combine partials -> em_s PRE-EXPONENTIATED; trans_e; masks ----
    const int mw = s_mw, gw = s_gw;
#pragma unroll
    for (int pass = 0; pass < 4; pass++) {
        int idx = pass * 128 + t;          // 0..511
        int r = idx >> 3, k = idx & 7;
        float e = 0.f;
        if (k < 7) {
            float raw = wsum[0][r][k] + wsum[1][r][k] + wsum[2][r][k] + wsum[3][r][k] + bias[k];
            e = ex2f(raw * L2E);           // ONE ex2f per emission element
        }
        em_s[r][k] = e;
    }
    if (t < 49) trans_e[t] = ex2f(trans_s[t] * L2E);   // ONE ex2f per trans elem
    if (t < 64) msk_s[t] = mask[((long)b * SS + cc * 64 + t) * mw] ? 1 : 0;
    __syncthreads();

    if (cc == 0 && t < 7) g_em0[b * 7 + t] = lg2f(em_s[0][t]);  // log2 domain

    // ---- recursion: two 64-thread groups, one chunk each (no MUFU in loop) --
    {
        const int grp = t >> 6;            // 0 or 1
        const int u = t & 63;
        const int i = u >> 3, j = u & 7;
        const bool act = (i < 7) && (j < 7);
        const int jj = (j < 7) ? j : 0;
        const int base = grp * 32;         // local row base
        const int ch = cc * 2 + grp;       // chunk within batch

        float Tr[7];
#pragma unroll
        for (int k = 0; k < 7; k++)
            Tr[k] = act ? trans_e[k * 7 + jj] : 0.f;

        float v = (act && i == j) ? 1.f : 0.f;
        int mexp = 0;

#pragma unroll 1
        for (int g4 = 0; g4 < 8; g4++) {
#pragma unroll
            for (int q = 0; q < 4; q++) {
                const int lt = g4 * 4 + q;
                float e = em_s[base + lt][jj];      // pre-exponentiated
                int mk = msk_s[base + lt];
                if (ch == 0 && lt == 0) mk = 0;     // global step 0 excluded
                float nv = 0.f;
#pragma unroll
                for (int k = 0; k < 7; k++)
                    nv = fmaf(__shfl_sync(0xffffffffu, v, k, 8), Tr[k], nv);
                if (mk) v = nv * e;
            }
            float rs = v;
            rs += __shfl_xor_sync(0xffffffffu, rs, 4, 8);
            rs += __shfl_xor_sync(0xffffffffu, rs, 2, 8);
            rs += __shfl_xor_sync(0xffffffffu, rs, 1, 8);
            int eb = ((__float_as_int(rs) >> 23) & 255) - 127;
            eb = (rs > 0.f) ? eb : 0;
            v *= __int_as_float((127 - eb) << 23);   // * 2^-eb
            mexp += eb;
        }
        if (act)
            g_M[(long)(b * NCHUNK + ch) * 49 + i * 7 + j] = (float)mexp + lg2f(v);
    }

    // ---- numerator partial for this block's 64 timesteps (warp 0) ----
    if (warp == 0) {
        float ns = 0.f;
        int nc = 0;
#pragma unroll
        for (int q = 0; q < 2; q++) {
            int lt = lane * 2 + q;
            int t_abs = cc * 64 + lt;
            int gc = ((const int*)gt)[((long)b * SS + t_abs) * gw];
            int m = msk_s[lt];
            nc += m;
            float emv = lg2f(em_s[lt][gc]) * LN2;   // recover raw emission
            if (t_abs == 0) {
                ns += start_t[gc] + emv;
            } else {
                int gp = ((const int*)gt)[((long)b * SS + t_abs - 1) * gw];
                ns += m ? (trans_s[gp * 7 + gc] + emv) : 0.f;
            }
        }
#pragma unroll
        for (int off = 16; off; off >>= 1) {
            ns += __shfl_xor_sync(0xffffffffu, ns, off);
            nc += __shfl_xor_sync(0xffffffffu, nc, off);
        }
        if (lane == 0) { g_nump[g] = ns; g_cntp[g] = nc; }
    }

    // ---- publish + per-batch election ----
    __threadfence();
    __syncthreads();
    if (t == 0) {
        unsigned int old = atomicInc(&g_bcnt[b], 7u);
        s_last = (old == 7u) ? 1 : 0;
    }
    __syncthreads();
    if (!s_last || warp != 0) return;
    __threadfence();

    // ---- batch combine (warp 0 of the finisher; inputs L2-hot) ----
    {
        const int j = lane & 7;
        const int jj = (j < 7) ? j : 0;

        float p = (lane < 8) ? __ldcg(&g_nump[b * 8 + lane]) : 0.f;
        int cn = (lane < 8) ? __ldcg(&g_cntp[b * 8 + lane]) : 0;
#pragma unroll
        for (int off = 16; off; off >>= 1) {
            p += __shfl_xor_sync(0xffffffffu, p, off);
            cn += __shfl_xor_sync(0xffffffffu, cn, off);
        }
        const float num = p + end_t[((const int*)gt)[((long)b * SS + cn - 1) * gw]];

        float a = (j < 7) ? start_t[jj] * L2E + __ldcg(&g_em0[b * 7 + jj]) : -1e30f;
        float M[7], M2[7];
#pragma unroll
        for (int i2 = 0; i2 < 7; i2++)
            M[i2] = __ldcg(&g_M[(long)(b * NCHUNK) * 49 + i2 * 7 + jj]);

        for (int ch = 0; ch < NCHUNK; ch++) {
            if (ch + 1 < NCHUNK) {
#pragma unroll
                for (int i2 = 0; i2 < 7; i2++)
                    M2[i2] = __ldcg(&g_M[(long)(b * NCHUNK + ch + 1) * 49 + i2 * 7 + jj]);
            }
            float mx = -1e30f;
            float vv[7];
#pragma unroll
            for (int i2 = 0; i2 < 7; i2++) {
                vv[i2] = __shfl_sync(0xffffffffu, a, i2, 8) + M[i2];
                mx = fmaxf(mx, vv[i2]);
            }
            float sum = 0.f;
#pragma unroll
            for (int i2 = 0; i2 < 7; i2++) sum += ex2f(vv[i2] - mx);
            float anew = mx + lg2f(sum);
            a = (j < 7) ? anew : -1e30f;
#pragma unroll
            for (int i2 = 0; i2 < 7; i2++) M[i2] = M2[i2];
        }

        float z = (j < 7) ? a + end_t[jj] * L2E : -1e30f;
        float mz = z;
#pragma unroll
        for (int off = 4; off; off >>= 1)
            mz = fmaxf(mz, __shfl_xor_sync(0xffffffffu, mz, off, 8));
        float se = ex2f(z - mz);
#pragma unroll
        for (int off = 4; off; off >>= 1)
            se += __shfl_xor_sync(0xffffffffu, se, off, 8);
        const float denom = (mz + lg2f(se)) * LN2;

        if (lane == 0) {
            atomicAdd(&g_llh, num - denom);
            __threadfence();
            unsigned int old = atomicInc(&g_done, BB - 1);
            if (old == BB - 1) {
                float tot = atomicExch(&g_llh, 0.f);
                out[0] = -tot / (float)BB;
            }
        }
    }
}

// ---------------------------------------------------------------------------
extern "C" void kernel_launch(void* const* d_in, const int* in_sizes, int n_in,
                              void* d_out, int out_size) {
    const float4* x = (const float4*)d_in[0];
    const void* gt = d_in[1];
    const unsigned char* mask = (const unsigned char*)d_in[2];
    const float* W = (const float*)d_in[3];
    const float* bias = (const float*)d_in[4];
    const float* start_t = (const float*)d_in[5];
    const float* end_t = (const float*)d_in[6];
    const float* trans = (const float*)d_in[7];
    float* out = (float*)d_out;

    k_one<<<NBLK, 128>>>(x, W, bias, gt, mask, start_t, end_t, trans, out);
}